// round 4
// baseline (speedup 1.0000x reference)
#include <cuda_runtime.h>
#include <cuda_bf16.h>
#include <cstdint>

// ---------------- problem constants ----------------
#define N_ROWS   16384
#define N_CODES  8192
#define DIM      512
#define Q_ELEMS  (N_ROWS * DIM)

// ---------------- GEMM tiling ----------------
#define BM 256
#define BN 128
#define KC 64                 // K elems per stage (bf16) = 128 B per row
#define NSTAGES (DIM / KC)    // 8
#define NPIPE 3
#define CH 8                  // codes per argmin chunk
#define NCH (N_CODES / CH)    // 1024 chunk-mins per row
#define EPS 5.0e-4f

// dynamic smem: 3 stages x (A 32KB + B 16KB) = 147456, enorm (128 floats) after
#define STG_BYTES 49152
#define SM_BOFF   32768
#define SM_ENORM  147456
#define SM_TOTAL  (147456 + 512)

// ---------------- scratch (device globals; no allocation allowed) ----------------
__device__ __align__(256) __nv_bfloat16 g_hx[(size_t)N_ROWS * DIM];
__device__ __align__(256) __nv_bfloat16 g_he[(size_t)N_CODES * DIM];
__device__ float g_xnorm[N_ROWS];
__device__ float g_enorm[N_CODES];
__device__ float g_cmin[(size_t)N_ROWS * NCH];
__device__ float g_rowsq[N_ROWS];
__device__ int   g_maxidx;

// ---------------- PTX helpers ----------------
__device__ __forceinline__ uint32_t smem_u32(const void* p) {
    uint32_t a;
    asm("{ .reg .u64 t; cvta.to.shared.u64 t, %1; cvt.u32.u64 %0, t; }"
        : "=r"(a) : "l"(p));
    return a;
}
__device__ __forceinline__ void cp16(uint32_t dst, const void* src) {
    asm volatile("cp.async.cg.shared.global [%0], [%1], 16;" :: "r"(dst), "l"(src) : "memory");
}
#define CP_COMMIT() asm volatile("cp.async.commit_group;" ::: "memory")
#define CP_WAIT(n)  asm volatile("cp.async.wait_group %0;" :: "n"(n) : "memory")

#define SWZ(b) ((b) ^ (((b) >> 3) & 0x70))

__device__ __forceinline__ void ldsm4(uint32_t* r, uint32_t addr) {
    asm volatile("ldmatrix.sync.aligned.m8n8.x4.shared.b16 {%0,%1,%2,%3}, [%4];"
                 : "=r"(r[0]), "=r"(r[1]), "=r"(r[2]), "=r"(r[3]) : "r"(addr));
}
__device__ __forceinline__ void mma16816(float* c, const uint32_t* a, const uint32_t* b) {
    asm volatile(
        "mma.sync.aligned.m16n8k16.row.col.f32.bf16.bf16.f32 "
        "{%0,%1,%2,%3}, {%4,%5,%6,%7}, {%8,%9}, {%0,%1,%2,%3};"
        : "+f"(c[0]), "+f"(c[1]), "+f"(c[2]), "+f"(c[3])
        : "r"(a[0]), "r"(a[1]), "r"(a[2]), "r"(a[3]), "r"(b[0]), "r"(b[1]));
}

// ---------------- kernels ----------------
__global__ void init_kernel() { g_maxidx = 0; }

// one warp per row: fp32 norm + bf16 convert
__global__ void convert_kernel(const float* __restrict__ x, const float* __restrict__ emb) {
    int warp = (blockIdx.x * blockDim.x + threadIdx.x) >> 5;
    int lane = threadIdx.x & 31;
    const float* src; __nv_bfloat16* dst; float* nrm; int row;
    if (warp < N_ROWS) { src = x; dst = g_hx; nrm = g_xnorm; row = warp; }
    else               { src = emb; dst = g_he; nrm = g_enorm; row = warp - N_ROWS; }
    const float4* p = reinterpret_cast<const float4*>(src + (size_t)row * DIM);
    uint2* o = reinterpret_cast<uint2*>(dst + (size_t)row * DIM);
    float s = 0.f;
    #pragma unroll
    for (int c = lane; c < DIM / 4; c += 32) {
        float4 v = p[c];
        s += v.x * v.x + v.y * v.y + v.z * v.z + v.w * v.w;
        __nv_bfloat162 lo = __floats2bfloat162_rn(v.x, v.y);
        __nv_bfloat162 hi = __floats2bfloat162_rn(v.z, v.w);
        uint2 u;
        u.x = *reinterpret_cast<unsigned*>(&lo);
        u.y = *reinterpret_cast<unsigned*>(&hi);
        o[c] = u;
    }
    #pragma unroll
    for (int off = 16; off; off >>= 1) s += __shfl_xor_sync(0xffffffffu, s, off);
    if (lane == 0) nrm[row] = s;
}

// fast bf16 HMMA GEMM: per CTA 256 rows x 128 codes x K=512, 512 threads, 3-stage.
// Epilogue: d~ = enorm - 2*dot, per-row min over 8-code chunks -> g_cmin.
__global__ void __launch_bounds__(512, 1) vq_gemm_kernel() {
    extern __shared__ __align__(1024) char smem[];
    const int tid = threadIdx.x;
    const int w = tid >> 5, l = tid & 31;
    const int rowBase = blockIdx.x * BM;
    const int cb = blockIdx.y * BN;
    const uint32_t sb = smem_u32(smem);
    float* senorm = reinterpret_cast<float*>(smem + SM_ENORM);

    if (tid < BN) senorm[tid] = g_enorm[cb + tid];

    // warp layout: 4 (M) x 4 (N); warp tile 64 x 32
    const int m0 = (w >> 2) * 64;
    const int n0 = (w & 3) * 32;

    // ldmatrix lane addressing
    const int aRowLane = l & 15;
    const int aChunkHi = l >> 4;
    const int bRowLane = ((l >> 4) & 1) * 8 + (l & 7);
    const int bChunkHi = (l >> 3) & 1;

    float c[4][4][4];
    #pragma unroll
    for (int mt = 0; mt < 4; mt++)
        #pragma unroll
        for (int nt = 0; nt < 4; nt++)
            #pragma unroll
            for (int e = 0; e < 4; e++) c[mt][nt][e] = 0.f;

    // stage loader: K chunk kc -> stage buffer s (ends with commit)
    auto load_stage = [&](int kc, int s) {
        const int kb = kc * KC;
        const uint32_t stg = sb + (uint32_t)s * STG_BYTES;
        #pragma unroll
        for (int q = 0; q < 4; q++) {            // A: 256 rows x 8 chunks
            int t = tid + q * 512;
            int r = t >> 3, ch = t & 7;
            cp16(stg + SWZ((uint32_t)(r * 128 + ch * 16)),
                 g_hx + (size_t)(rowBase + r) * DIM + kb + ch * 8);
        }
        #pragma unroll
        for (int q = 0; q < 2; q++) {            // B: 128 rows x 8 chunks
            int t = tid + q * 512;
            int r = t >> 3, ch = t & 7;
            cp16(stg + SM_BOFF + SWZ((uint32_t)(r * 128 + ch * 16)),
                 g_he + (size_t)(cb + r) * DIM + kb + ch * 8);
        }
        CP_COMMIT();
    };

    load_stage(0, 0);
    load_stage(1, 1);
    load_stage(2, 2);

    int buf = 0;
    for (int i = 0; i < NSTAGES; i++) {
        CP_WAIT(2);
        __syncthreads();
        const uint32_t aStg = sb + (uint32_t)buf * STG_BYTES;
        const uint32_t bStg = aStg + SM_BOFF;
        #pragma unroll
        for (int ks = 0; ks < 4; ks++) {
            uint32_t a[4][4], b[4][2];
            #pragma unroll
            for (int mt = 0; mt < 4; mt++) {
                uint32_t off = (uint32_t)((m0 + mt * 16 + aRowLane) * 128
                                          + (ks * 2 + aChunkHi) * 16);
                ldsm4(a[mt], aStg + SWZ(off));
            }
            #pragma unroll
            for (int nt2 = 0; nt2 < 2; nt2++) {
                uint32_t r4[4];
                uint32_t off = (uint32_t)((n0 + nt2 * 16 + bRowLane) * 128
                                          + (ks * 2 + bChunkHi) * 16);
                ldsm4(r4, bStg + SWZ(off));
                b[nt2 * 2][0] = r4[0]; b[nt2 * 2][1] = r4[1];
                b[nt2 * 2 + 1][0] = r4[2]; b[nt2 * 2 + 1][1] = r4[3];
            }
            #pragma unroll
            for (int mt = 0; mt < 4; mt++)
                #pragma unroll
                for (int nt = 0; nt < 4; nt++)
                    mma16816(c[mt][nt], a[mt], b[nt]);
        }
        __syncthreads();
        if (i + NPIPE < NSTAGES) load_stage(i + NPIPE, buf);
        else CP_COMMIT();                        // keep wait-depth invariant at drain
        buf = (buf + 1 == NPIPE) ? 0 : buf + 1;
    }

    // ---- epilogue: chunk (8-code) mins -> smem staging -> coalesced gmem
    __syncthreads();                             // stage buffers free; [256][20] floats
    float* sbuf = reinterpret_cast<float*>(smem);

    const int j0 = (l & 3) * 2;
    #pragma unroll
    for (int mt = 0; mt < 4; mt++) {
        #pragma unroll
        for (int nt = 0; nt < 4; nt++) {
            const int colBase = n0 + nt * 8 + j0;
            float en0 = senorm[colBase], en1 = senorm[colBase + 1];
            float v0 = fminf(en0 - 2.0f * c[mt][nt][0], en1 - 2.0f * c[mt][nt][1]);
            float v1 = fminf(en0 - 2.0f * c[mt][nt][2], en1 - 2.0f * c[mt][nt][3]);
            #pragma unroll
            for (int off = 1; off <= 2; off <<= 1) {
                v0 = fminf(v0, __shfl_xor_sync(0xffffffffu, v0, off));
                v1 = fminf(v1, __shfl_xor_sync(0xffffffffu, v1, off));
            }
            if ((l & 3) == 0) {
                int rloc = m0 + mt * 16 + (l >> 2);
                int chLoc = (w & 3) * 4 + nt;            // 0..15
                sbuf[rloc * 20 + chLoc] = v0;
                sbuf[(rloc + 8) * 20 + chLoc] = v1;
            }
        }
    }
    __syncthreads();
    {
        int row = tid >> 1, half = tid & 1;
        const float* s = &sbuf[row * 20 + half * 8];
        float4 o0 = make_float4(s[0], s[1], s[2], s[3]);
        float4 o1 = make_float4(s[4], s[5], s[6], s[7]);
        float* dst = &g_cmin[(size_t)(rowBase + row) * NCH + blockIdx.y * 16 + half * 8];
        reinterpret_cast<float4*>(dst)[0] = o0;
        reinterpret_cast<float4*>(dst)[1] = o1;
    }
}

// warp-per-row exact rescore + gather + straight-through + rowsq.
// block 256 (8 warps = 8 rows), grid N_ROWS/8.
__global__ void __launch_bounds__(256) rescore_kernel(const float* __restrict__ x,
                                                      const float* __restrict__ emb,
                                                      float* __restrict__ out) {
    const int lane = threadIdx.x & 31;
    const int row = blockIdx.x * 8 + (threadIdx.x >> 5);

    // x row resident in registers (4 float4 per lane, stride-32 layout)
    const float4* x4 = reinterpret_cast<const float4*>(x + (size_t)row * DIM);
    float4 xv[4];
    #pragma unroll
    for (int t = 0; t < 4; t++) xv[t] = x4[t * 32 + lane];

    // scan 1024 chunk mins
    const float4* cm4 = reinterpret_cast<const float4*>(&g_cmin[(size_t)row * NCH]);
    float4 cv[8];
    float lmin = 3.4028235e38f;
    #pragma unroll
    for (int q = 0; q < 8; q++) {
        cv[q] = cm4[q * 32 + lane];
        lmin = fminf(fminf(fminf(lmin, cv[q].x), fminf(cv[q].y, cv[q].z)), cv[q].w);
    }
    #pragma unroll
    for (int off = 16; off; off >>= 1) lmin = fminf(lmin, __shfl_xor_sync(0xffffffffu, lmin, off));
    const float thr = lmin + EPS;

    const float xn = g_xnorm[row];
    float bestd = 3.4028235e38f;
    int besti = 0x7fffffff;

    #pragma unroll
    for (int q = 0; q < 8; q++) {
        #pragma unroll
        for (int e = 0; e < 4; e++) {
            float ve = (&cv[q].x)[e];
            unsigned m = __ballot_sync(0xffffffffu, ve <= thr);
            while (m) {
                int b = __ffs(m) - 1;
                m &= m - 1;
                int ci = (q * 32 + b) * 4 + e;
                #pragma unroll 1
                for (int cc = 0; cc < CH; cc++) {
                    int code = ci * CH + cc;
                    const float4* e4 = reinterpret_cast<const float4*>(emb + (size_t)code * DIM);
                    float acc = 0.f;
                    #pragma unroll
                    for (int t = 0; t < 4; t++) {
                        float4 ev = e4[t * 32 + lane];
                        acc = fmaf(ev.x, xv[t].x, acc);
                        acc = fmaf(ev.y, xv[t].y, acc);
                        acc = fmaf(ev.z, xv[t].z, acc);
                        acc = fmaf(ev.w, xv[t].w, acc);
                    }
                    #pragma unroll
                    for (int off = 16; off; off >>= 1)
                        acc += __shfl_xor_sync(0xffffffffu, acc, off);
                    float d = __fsub_rn(__fadd_rn(xn, g_enorm[code]), 2.0f * acc);
                    if (d < bestd || (d == bestd && code < besti)) { bestd = d; besti = code; }
                }
            }
        }
    }

    if (lane == 0) {
        out[Q_ELEMS + 2 + row] = (float)besti;
        atomicMax(&g_maxidx, besti);
    }

    // gather + straight-through + rowsq
    const float4* q4p = reinterpret_cast<const float4*>(emb + (size_t)besti * DIM);
    float ss = 0.f;
    #pragma unroll
    for (int t = 0; t < 4; t++) {
        float4 qv = q4p[t * 32 + lane];
        float4 xr = xv[t];
        float4 o4;
        float d0 = __fsub_rn(qv.x, xr.x); o4.x = __fadd_rn(xr.x, d0); ss += d0 * d0;
        float d1 = __fsub_rn(qv.y, xr.y); o4.y = __fadd_rn(xr.y, d1); ss += d1 * d1;
        float d2 = __fsub_rn(qv.z, xr.z); o4.z = __fadd_rn(xr.z, d2); ss += d2 * d2;
        float d3 = __fsub_rn(qv.w, xr.w); o4.w = __fadd_rn(xr.w, d3); ss += d3 * d3;
        reinterpret_cast<float4*>(out + (size_t)row * DIM)[t * 32 + lane] = o4;
    }
    #pragma unroll
    for (int off = 16; off; off >>= 1) ss += __shfl_xor_sync(0xffffffffu, ss, off);
    if (lane == 0) g_rowsq[row] = ss;
}

__global__ void scalars_kernel(float* __restrict__ out) {
    __shared__ float red[1024];
    const int tid = threadIdx.x;
    float s = 0.f;
    for (int r = tid; r < N_ROWS; r += 1024) s += g_rowsq[r];
    red[tid] = s;
    __syncthreads();
    #pragma unroll
    for (int st = 512; st > 0; st >>= 1) {
        if (tid < st) red[tid] += red[tid + st];
        __syncthreads();
    }
    if (tid == 0) {
        float mean = red[0] / (float)Q_ELEMS;
        out[Q_ELEMS] = 1.25f * mean;
        float L = (float)(g_maxidx + 1);
        float avg = 1.0f / L;
        out[Q_ELEMS + 1] = expf(-avg * logf(avg + 1e-10f));
    }
}

extern "C" void kernel_launch(void* const* d_in, const int* in_sizes, int n_in,
                              void* d_out, int out_size) {
    const float* x   = (const float*)d_in[0];
    const float* emb = (const float*)d_in[1];
    float* out = (float*)d_out;

    cudaFuncSetAttribute(vq_gemm_kernel, cudaFuncAttributeMaxDynamicSharedMemorySize, SM_TOTAL);

    init_kernel<<<1, 1>>>();
    convert_kernel<<<(N_ROWS + N_CODES) / 8, 256>>>(x, emb);
    vq_gemm_kernel<<<dim3(N_ROWS / BM, N_CODES / BN), 512, SM_TOTAL>>>();
    rescore_kernel<<<N_ROWS / 8, 256>>>(x, emb, out);
    scalars_kernel<<<1, 1024>>>(out);
}